// round 10
// baseline (speedup 1.0000x reference)
#include <cuda_runtime.h>
#include <cuda_bf16.h>
#include <math_constants.h>

// Deterministic in-kernel dtype detection (int64 vs int32 index map), using
// only reads in-bounds for BOTH interpretations: first 32 bytes = 8 int32
// words. int64 buffer (indices < 2^31) -> odd words (high halves) all zero.
// int32 permutation -> at most one of words {1,3,5,7} is zero.
__device__ __forceinline__ bool map_is_int64(const void* imap) {
    const uint4* w = (const uint4*)imap;
    uint4 a = __ldg(w + 0);
    uint4 b = __ldg(w + 1);
    return ((a.y | a.w | b.y | b.w) == 0u);
}

__device__ __forceinline__ float4 f4max(float4 a, float4 b) {
    a.x = fmaxf(a.x, b.x); a.y = fmaxf(a.y, b.y);
    a.z = fmaxf(a.z, b.z); a.w = fmaxf(a.w, b.w);
    return a;
}

// Fast path: C == 96 (24 float4 chunks), KV == 8.
// Thread t = (output o, chunk j): 8 independent LDG.128 + 1 STG.128 per
// thread, 32 regs. 256-thread blocks -> 8 CTAs x 8 warps = 64/64 warps/SM
// (100% theoretical occupancy; the R5 192-thread shape capped at 60/64).
// Max resident light warps is the proven lever for DRAM% on this gather.
__global__ __launch_bounds__(256)
void sparse_maxpool_c96(const float4* __restrict__ feat,
                        const void* __restrict__ imap,
                        float4* __restrict__ out, int n_out) {
    int t = blockIdx.x * 256 + threadIdx.x;
    int o = t / 24;
    int j = t - o * 24;
    if (o >= n_out) return;

    int idx[8];
    if (map_is_int64(imap)) {
        // 8 int64 = 64B = 4 x uint4; low word of each half is the index.
        const uint4* mp = (const uint4*)((const char*)imap + (size_t)o * 64);
        uint4 q0 = __ldg(mp + 0);
        uint4 q1 = __ldg(mp + 1);
        uint4 q2 = __ldg(mp + 2);
        uint4 q3 = __ldg(mp + 3);
        idx[0] = (int)q0.x; idx[1] = (int)q0.z;
        idx[2] = (int)q1.x; idx[3] = (int)q1.z;
        idx[4] = (int)q2.x; idx[5] = (int)q2.z;
        idx[6] = (int)q3.x; idx[7] = (int)q3.z;
    } else {
        // 8 int32 = 32B = 2 x uint4.
        const uint4* mp = (const uint4*)((const char*)imap + (size_t)o * 32);
        uint4 q0 = __ldg(mp + 0);
        uint4 q1 = __ldg(mp + 1);
        idx[0] = (int)q0.x; idx[1] = (int)q0.y;
        idx[2] = (int)q0.z; idx[3] = (int)q0.w;
        idx[4] = (int)q1.x; idx[5] = (int)q1.y;
        idx[6] = (int)q1.z; idx[7] = (int)q1.w;
    }

    // 8 independent streaming 16B loads (each row read exactly once).
    float4 v = __ldcs(feat + (size_t)idx[0] * 24 + j);
#pragma unroll
    for (int k = 1; k < 8; k++)
        v = f4max(v, __ldcs(feat + (size_t)idx[k] * 24 + j));

    __stcs(out + (size_t)o * 24 + j, v);
}

// Generic fallback: any C, any KV. Warp per output.
__global__ __launch_bounds__(256)
void sparse_maxpool_generic(const float* __restrict__ feat,
                            const void* __restrict__ imap,
                            float* __restrict__ out,
                            int n_out, int C, int KV) {
    int gw   = (int)((blockIdx.x * (long long)blockDim.x + threadIdx.x) >> 5);
    int lane = threadIdx.x & 31;
    if (gw >= n_out) return;

    const bool is64 = map_is_int64(imap);
    const long long* m64 = (const long long*)imap;
    const int*       m32 = (const int*)imap;
    long long base = (long long)gw * KV;

    for (int c0 = 0; c0 < C; c0 += 32) {
        int c = c0 + lane;
        float v = -CUDART_INF_F;
        for (int k = 0; k < KV; k++) {
            long long r = is64 ? m64[base + k] : (long long)m32[base + k];
            if (c < C) v = fmaxf(v, __ldg(feat + r * (long long)C + c));
        }
        if (c < C) out[(long long)gw * C + c] = v;
    }
}

extern "C" void kernel_launch(void* const* d_in, const int* in_sizes, int n_in,
                              void* d_out, int out_size) {
    const float* feat = (const float*)d_in[0];
    const void*  imap = d_in[1];

    long long n_feat_elems = in_sizes[0];
    long long n_map        = in_sizes[1];
    int C     = (int)(n_feat_elems / n_map);   // 96
    int n_out = out_size / C;                  // 125000
    int KV    = (int)(n_map / n_out);          // 8

    if (C == 96 && KV == 8) {
        long long total = (long long)n_out * 24;
        int grid = (int)((total + 255) / 256);
        sparse_maxpool_c96<<<grid, 256>>>((const float4*)feat, imap,
                                          (float4*)d_out, n_out);
    } else {
        long long total_threads = (long long)n_out * 32;
        int grid = (int)((total_threads + 255) / 256);
        sparse_maxpool_generic<<<grid, 256>>>(feat, imap, (float*)d_out,
                                              n_out, C, KV);
    }
}

// round 14
// speedup vs baseline: 1.0076x; 1.0076x over previous
#include <cuda_runtime.h>
#include <cuda_bf16.h>
#include <math_constants.h>

// Deterministic in-kernel dtype detection (int64 vs int32 index map), using
// only reads in-bounds for BOTH interpretations: first 32 bytes = 8 int32
// words. int64 buffer (indices < 2^31) -> odd words (high halves) all zero.
// int32 permutation -> at most one of words {1,3,5,7} is zero.
__device__ __forceinline__ bool map_is_int64(const void* imap) {
    const uint4* w = (const uint4*)imap;
    uint4 a = __ldg(w + 0);
    uint4 b = __ldg(w + 1);
    return ((a.y | a.w | b.y | b.w) == 0u);
}

__device__ __forceinline__ float4 f4max(float4 a, float4 b) {
    a.x = fmaxf(a.x, b.x); a.y = fmaxf(a.y, b.y);
    a.z = fmaxf(a.z, b.z); a.w = fmaxf(a.w, b.w);
    return a;
}

// Fast path: C == 96 (24 float4 chunks), KV == 8.
// Empirically optimal shape (best of 5 structural variants swept R2-R10):
// thread t = (output o, chunk j); 192-thread blocks; 32 regs; 8 independent
// streaming LDG.128 + 1 STG.128 per thread. Pinned at DRAM ~78% — the
// device's random-384B-gather + streaming-write ceiling. Occupancy-heavy
// (R4/R6) and wider-block (R7) variants all measured equal or worse.
__global__ __launch_bounds__(192)
void sparse_maxpool_c96(const float4* __restrict__ feat,
                        const void* __restrict__ imap,
                        float4* __restrict__ out, int n_out) {
    int t = blockIdx.x * 192 + threadIdx.x;
    int o = t / 24;
    int j = t - o * 24;
    if (o >= n_out) return;

    int idx[8];
    if (map_is_int64(imap)) {
        const long long* m = (const long long*)imap;
#pragma unroll
        for (int k = 0; k < 8; k++) idx[k] = (int)m[o * 8 + k];
    } else {
        const int* m = (const int*)imap;
#pragma unroll
        for (int k = 0; k < 8; k++) idx[k] = m[o * 8 + k];
    }

    // 8 independent streaming 16B loads (each feature row read exactly once).
    float4 v = __ldcs(feat + (size_t)idx[0] * 24 + j);
#pragma unroll
    for (int k = 1; k < 8; k++)
        v = f4max(v, __ldcs(feat + (size_t)idx[k] * 24 + j));

    __stcs(out + (size_t)o * 24 + j, v);
}

// Generic fallback: any C, any KV. Warp per output.
__global__ __launch_bounds__(256)
void sparse_maxpool_generic(const float* __restrict__ feat,
                            const void* __restrict__ imap,
                            float* __restrict__ out,
                            int n_out, int C, int KV) {
    int gw   = (int)((blockIdx.x * (long long)blockDim.x + threadIdx.x) >> 5);
    int lane = threadIdx.x & 31;
    if (gw >= n_out) return;

    const bool is64 = map_is_int64(imap);
    const long long* m64 = (const long long*)imap;
    const int*       m32 = (const int*)imap;
    long long base = (long long)gw * KV;

    for (int c0 = 0; c0 < C; c0 += 32) {
        int c = c0 + lane;
        float v = -CUDART_INF_F;
        for (int k = 0; k < KV; k++) {
            long long r = is64 ? m64[base + k] : (long long)m32[base + k];
            if (c < C) v = fmaxf(v, __ldg(feat + r * (long long)C + c));
        }
        if (c < C) out[(long long)gw * C + c] = v;
    }
}

extern "C" void kernel_launch(void* const* d_in, const int* in_sizes, int n_in,
                              void* d_out, int out_size) {
    const float* feat = (const float*)d_in[0];
    const void*  imap = d_in[1];

    long long n_feat_elems = in_sizes[0];
    long long n_map        = in_sizes[1];
    int C     = (int)(n_feat_elems / n_map);   // 96
    int n_out = out_size / C;                  // 125000
    int KV    = (int)(n_map / n_out);          // 8

    if (C == 96 && KV == 8) {
        long long total = (long long)n_out * 24;
        int grid = (int)((total + 191) / 192);
        sparse_maxpool_c96<<<grid, 192>>>((const float4*)feat, imap,
                                          (float4*)d_out, n_out);
    } else {
        long long total_threads = (long long)n_out * 32;
        int grid = (int)((total_threads + 255) / 256);
        sparse_maxpool_generic<<<grid, 256>>>(feat, imap, (float*)d_out,
                                              n_out, C, KV);
    }
}